// round 14
// baseline (speedup 1.0000x reference)
#include <cuda_runtime.h>
#include <cstdint>

#define T_DIM  4096
#define B_DIM  8192
#define CHUNKS 128
#define CL     32               // chunk length; CHUNKS*CL == T_DIM
#define CP1    (CHUNKS + 1)
#define NBG    (B_DIM / 32)     // 256 bit-groups of 32 sequences

// Scratch: static device globals (allocation-free). ~16.3 MB total.
__device__ uint32_t g_bits[CHUNKS * B_DIM];      // 4 MB packed inputs
__device__ float    g_state[3][CHUNKS * B_DIM];  // 12 MB chunk states (n1t, n11, na1)
__device__ uint32_t g_pb[NBG * CP1];             // 129 KB prev-bit sidecar: [bg][c] = last bits of chunk c-1
__device__ uint32_t g_fb[NBG * CHUNKS];          // 128 KB first-bit sidecar: [bg][c] = first bits of chunk c

// ---------------------------------------------------------------------------
// Pass 1: chunk-local recurrence ASSUMING prev=0 (no prev-row read!).
// 4 seqs/thread, plain float4 loads. Emits bit sidecars via smem packing.
// ---------------------------------------------------------------------------
__global__ void __launch_bounds__(256) lk_pass1(const float* __restrict__ in,
                                                const float* __restrict__ dptr) {
    const float d = dptr[0];
    const int c  = blockIdx.y;
    const int g  = blockIdx.x * blockDim.x + threadIdx.x;
    const int b0 = g * 4;

    __shared__ uint32_t s_pb[32], s_fb[32];
    if (threadIdx.x < 32) { s_pb[threadIdx.x] = 0u; s_fb[threadIdx.x] = 0u; }
    __syncthreads();

    float prev_d[4] = {0.f, 0.f, 0.f, 0.f};   // symbolic prev = 0; corrected in pass2
    float n1t[4] = {0.f, 0.f, 0.f, 0.f};      // n10 + n11
    float n11[4] = {0.f, 0.f, 0.f, 0.f};
    float na1[4] = {0.f, 0.f, 0.f, 0.f};
    uint32_t bw[4] = {0u, 0u, 0u, 0u};

    const float4* __restrict__ p = (const float4*)(in + (size_t)(c * CL) * B_DIM + b0);

#pragma unroll
    for (int i = 0; i < CL; ++i) {
        float4 x4 = p[(size_t)i * (B_DIM / 4)];
        float xs[4] = {x4.x, x4.y, x4.z, x4.w};
#pragma unroll
        for (int s = 0; s < 4; ++s) {
            float curf = xs[s];                // 0.0f or 1.0f
            if (curf != 0.f) bw[s] |= (1u << i);
            float cur_d = curf * d;
            n11[s] = fmaf(d, n11[s], curf * prev_d[s]);
            na1[s] = fmaf(d, na1[s], prev_d[s]);
            n1t[s] = fmaf(d, n1t[s], cur_d);
            prev_d[s] = cur_d;
        }
    }

    *(uint4*)(g_bits + (size_t)c * B_DIM + b0) = make_uint4(bw[0], bw[1], bw[2], bw[3]);
    const size_t si = (size_t)c * B_DIM + b0;
    *(float4*)(&g_state[0][si]) = make_float4(n1t[0], n1t[1], n1t[2], n1t[3]);
    *(float4*)(&g_state[1][si]) = make_float4(n11[0], n11[1], n11[2], n11[3]);
    *(float4*)(&g_state[2][si]) = make_float4(na1[0], na1[1], na1[2], na1[3]);

    // Pack last/first bits: 4 bits per thread at nibble (tid%8)*4 of word tid/8.
    uint32_t nib_last = ((bw[0] >> 31) & 1u) | (((bw[1] >> 31) & 1u) << 1)
                      | (((bw[2] >> 31) & 1u) << 2) | (((bw[3] >> 31) & 1u) << 3);
    uint32_t nib_first = (bw[0] & 1u) | ((bw[1] & 1u) << 1)
                       | ((bw[2] & 1u) << 2) | ((bw[3] & 1u) << 3);
    int sh = (threadIdx.x & 7) * 4;
    if (nib_last)  atomicOr(&s_pb[threadIdx.x >> 3], nib_last << sh);
    if (nib_first) atomicOr(&s_fb[threadIdx.x >> 3], nib_first << sh);
    __syncthreads();

    if (threadIdx.x < 32) {
        int bg = blockIdx.x * 32 + threadIdx.x;
        g_pb[(size_t)bg * CP1 + (c + 1)] = s_pb[threadIdx.x];  // prev bits for chunk c+1
        g_fb[(size_t)bg * CHUNKS + c]    = s_fb[threadIdx.x];
        if (c == 0) g_pb[(size_t)bg * CP1] = 0u;               // chunk 0 has no prev
    }
}

// ---------------------------------------------------------------------------
// Pass 2: exclusive scan over chunk states with affine prev-bit correction:
// true_local = local(p=0) + p*x0*d^CL (n11) / + p*d^CL (na1).
// ---------------------------------------------------------------------------
__global__ void __launch_bounds__(256) lk_pass2(const float* __restrict__ dptr) {
    const float d = dptr[0];
    float dL = d;
#pragma unroll
    for (int i = 0; i < 5; ++i) dL *= dL;  // d^CL

    const int comp = blockIdx.y;  // 0=n1t (no corr), 1=n11, 2=na1
    const int b    = blockIdx.x * blockDim.x + threadIdx.x;
    const int bg   = b >> 5;
    const int sh   = b & 31;
    float* a = g_state[comp];

    float acc = 0.f;
#pragma unroll
    for (int batch = 0; batch < CHUNKS / 32; ++batch) {
        float v[32];
#pragma unroll
        for (int j = 0; j < 32; ++j)
            v[j] = a[(size_t)(batch * 32 + j) * B_DIM + b];

        if (comp != 0) {
#pragma unroll
            for (int j = 0; j < 32; ++j) {
                int c = batch * 32 + j;
                uint32_t pw = g_pb[(size_t)bg * CP1 + c];
                bool hit;
                if (comp == 1) {
                    uint32_t fw = g_fb[(size_t)bg * CHUNKS + c];
                    hit = ((pw & fw) >> sh) & 1u;
                } else {
                    hit = (pw >> sh) & 1u;
                }
                if (hit) v[j] += dL;
            }
        }
#pragma unroll
        for (int j = 0; j < 32; ++j) {
            float nv = fmaf(dL, acc, v[j]);
            v[j] = acc;           // exclusive prefix (corrected carry-in)
            acc = nv;
        }
#pragma unroll
        for (int j = 0; j < 32; ++j)
            a[(size_t)(batch * 32 + j) * B_DIM + b] = v[j];
    }
}

// ---------------------------------------------------------------------------
// Pass 3 (R4-proven shape): replay from corrected init; emit predictions.
// 2 seqs/thread, STG.64.cs, 2048 blocks x 256 threads. Prev bit from sidecar.
// ---------------------------------------------------------------------------
__global__ void __launch_bounds__(256, 6) lk_pass3(const float* __restrict__ dptr,
                                                   float* __restrict__ out) {
    const float d = dptr[0];
    const int c  = blockIdx.y;
    const int t  = blockIdx.x * blockDim.x + threadIdx.x;
    const int b0 = t * 2;
    const size_t si = (size_t)c * B_DIM + b0;

    float2 v1t = *(const float2*)(&g_state[0][si]);
    float2 v11 = *(const float2*)(&g_state[1][si]);
    float2 va1 = *(const float2*)(&g_state[2][si]);
    float n1t[2] = {v1t.x, v1t.y};
    float n11[2] = {v11.x, v11.y};
    float na1[2] = {va1.x, va1.y};

    // Deterministic total-count carry-in: S = d * (1 - d^{c*CL}) / (1 - d)
    float dL = d;
#pragma unroll
    for (int i = 0; i < 5; ++i) dL *= dL;   // d^CL
    float dcs = 1.f, base = dL;
    int e = c;
    while (e) { if (e & 1) dcs *= base; base *= base; e >>= 1; }
    float S = (c == 0) ? 0.f : d * (1.f - dcs) / (1.f - d);

    // prev bits from sidecar (slot c; zeroed for c==0 -> no branch)
    uint32_t pw = g_pb[(size_t)(b0 >> 5) * CP1 + c];
    float prev_d[2];
    prev_d[0] = ((pw >> (b0 & 31)) & 1u) ? d : 0.f;
    prev_d[1] = ((pw >> ((b0 & 31) + 1)) & 1u) ? d : 0.f;

    uint2 bwv = *(const uint2*)(g_bits + (size_t)c * B_DIM + b0);
    uint32_t bw[2] = {bwv.x, bwv.y};

    float2* __restrict__ po = (float2*)(out + (size_t)(c * CL) * B_DIM + b0);

#pragma unroll
    for (int i = 0; i < CL; ++i) {
        S = fmaf(d, S, d);  // shared across the sequences
        float ov[2];
#pragma unroll
        for (int s = 0; s < 2; ++s) {
            bool cur = (bw[s] >> i) & 1u;
            float cur_d = cur ? d : 0.f;
            n11[s] = fmaf(d, n11[s], cur ? prev_d[s] : 0.f);
            na1[s] = fmaf(d, na1[s], prev_d[s]);
            n1t[s] = fmaf(d, n1t[s], cur_d);
            prev_d[s] = cur_d;
            float num = (cur ? n11[s] : n1t[s] - n11[s]) + 1.f;
            float den = (cur ? na1[s] : S - na1[s]) + 2.f;
            ov[s] = __fdividef(num, den);
        }
        __stcs(po + (size_t)i * (B_DIM / 2), make_float2(ov[0], ov[1]));
    }
}

// ---------------------------------------------------------------------------
extern "C" void kernel_launch(void* const* d_in, const int* in_sizes, int n_in,
                              void* d_out, int out_size) {
    const float* in   = (const float*)d_in[0];
    const float* dptr = (const float*)d_in[1];
    if (n_in >= 2 && in_sizes[0] == 1) {  // defensive: metadata order swap
        in   = (const float*)d_in[1];
        dptr = (const float*)d_in[0];
    }
    float* out = (float*)d_out;

    dim3 blk(256);
    dim3 grid1((B_DIM / 4) / 256, CHUNKS);   // (8, 128)  = 1024 blocks
    dim3 grid2(B_DIM / 256, 3);              // (32, 3)
    dim3 grid3((B_DIM / 2) / 256, CHUNKS);   // (16, 128) = 2048 blocks

    lk_pass1<<<grid1, blk>>>(in, dptr);
    lk_pass2<<<grid2, blk>>>(dptr);
    lk_pass3<<<grid3, blk>>>(dptr, out);
}

// round 15
// speedup vs baseline: 1.4452x; 1.4452x over previous
#include <cuda_runtime.h>
#include <cstdint>

#define T_DIM  4096
#define B_DIM  8192
#define CHUNKS 128
#define CL     32          // chunk length; CHUNKS*CL == T_DIM

// Scratch: static device globals (allocation-free). 12 MB total.
// na1 is NOT stored: na1_t == n1t_{t-1} exactly (same recurrence, shifted input).
__device__ uint32_t g_bits[CHUNKS * B_DIM];          // 4 MB packed inputs
__device__ float    g_state[2][CHUNKS * B_DIM];      // 8 MB chunk states (n1t, n11)

// ---------------------------------------------------------------------------
// Pass 1 (R3-proven shape): per-chunk local recurrence; pack input bits.
// 4 seqs/thread, plain float4 loads, full unroll. Only 2 state components.
// ---------------------------------------------------------------------------
__global__ void __launch_bounds__(256) lk_pass1(const float* __restrict__ in,
                                                const float* __restrict__ dptr) {
    const float d = dptr[0];
    const int c  = blockIdx.y;
    const int g  = blockIdx.x * blockDim.x + threadIdx.x;
    const int b0 = g * 4;

    float prev_d[4] = {0.f, 0.f, 0.f, 0.f};
    if (c != 0) {
        float4 pv = *(const float4*)(in + (size_t)(c * CL - 1) * B_DIM + b0);
        prev_d[0] = pv.x * d; prev_d[1] = pv.y * d;
        prev_d[2] = pv.z * d; prev_d[3] = pv.w * d;
    }

    float n1t[4] = {0.f, 0.f, 0.f, 0.f};   // n10 + n11
    float n11[4] = {0.f, 0.f, 0.f, 0.f};
    uint32_t bw[4] = {0u, 0u, 0u, 0u};

    const float4* __restrict__ p = (const float4*)(in + (size_t)(c * CL) * B_DIM + b0);

#pragma unroll
    for (int i = 0; i < CL; ++i) {
        float4 x4 = p[(size_t)i * (B_DIM / 4)];
        float xs[4] = {x4.x, x4.y, x4.z, x4.w};
#pragma unroll
        for (int s = 0; s < 4; ++s) {
            float curf = xs[s];                    // 0.0f or 1.0f
            if (curf != 0.f) bw[s] |= (1u << i);
            float cur_d = curf * d;
            n11[s] = fmaf(d, n11[s], curf * prev_d[s]);
            n1t[s] = fmaf(d, n1t[s], cur_d);
            prev_d[s] = cur_d;
        }
    }

    *(uint4*)(g_bits + (size_t)c * B_DIM + b0) = make_uint4(bw[0], bw[1], bw[2], bw[3]);
    const size_t si = (size_t)c * B_DIM + b0;
    *(float4*)(&g_state[0][si]) = make_float4(n1t[0], n1t[1], n1t[2], n1t[3]);
    *(float4*)(&g_state[1][si]) = make_float4(n11[0], n11[1], n11[2], n11[3]);
}

// ---------------------------------------------------------------------------
// Pass 2 (R4-proven shape): exclusive scan over chunk states, in place.
// carry_c = local_c + d^CL * carry_{c-1}; 2 components only.
// ---------------------------------------------------------------------------
__global__ void __launch_bounds__(256) lk_pass2(const float* __restrict__ dptr) {
    const float d = dptr[0];
    float dL = d;
#pragma unroll
    for (int i = 0; i < 5; ++i) dL *= dL;  // d^32

    const int comp = blockIdx.y;  // 0..1
    const int b    = blockIdx.x * blockDim.x + threadIdx.x;
    float* a = g_state[comp];

    float acc = 0.f;
#pragma unroll
    for (int batch = 0; batch < CHUNKS / 32; ++batch) {
        float v[32];
#pragma unroll
        for (int j = 0; j < 32; ++j)
            v[j] = a[(size_t)(batch * 32 + j) * B_DIM + b];
#pragma unroll
        for (int j = 0; j < 32; ++j) {
            float nv = fmaf(dL, acc, v[j]);
            v[j] = acc;           // exclusive prefix
            acc = nv;
        }
#pragma unroll
        for (int j = 0; j < 32; ++j)
            a[(size_t)(batch * 32 + j) * B_DIM + b] = v[j];
    }
}

// ---------------------------------------------------------------------------
// Pass 3 (R4-proven shape): replay from corrected init; emit predictions.
// 2 seqs/thread, STG.64.cs, 2048 blocks x 256 threads.
// na1 is the PREVIOUS value of n1t (exact identity) — no third accumulator.
// ---------------------------------------------------------------------------
__global__ void __launch_bounds__(256, 6) lk_pass3(const float* __restrict__ dptr,
                                                   float* __restrict__ out) {
    const float d = dptr[0];
    const int c  = blockIdx.y;
    const int t  = blockIdx.x * blockDim.x + threadIdx.x;
    const int b0 = t * 2;
    const size_t si = (size_t)c * B_DIM + b0;

    float2 v1t = *(const float2*)(&g_state[0][si]);
    float2 v11 = *(const float2*)(&g_state[1][si]);
    float n1t[2] = {v1t.x, v1t.y};   // == n1t_{t0-1} == na1_{t0} for the first step
    float n11[2] = {v11.x, v11.y};

    // Deterministic total-count carry-in: S = d * (1 - d^{c*CL}) / (1 - d)
    float dL = d;
#pragma unroll
    for (int i = 0; i < 5; ++i) dL *= dL;   // d^CL
    float dcs = 1.f, base = dL;
    int e = c;
    while (e) { if (e & 1) dcs *= base; base *= base; e >>= 1; }
    float S = (c == 0) ? 0.f : d * (1.f - dcs) / (1.f - d);

    float prev_d[2] = {0.f, 0.f};
    if (c != 0) {
        uint2 pw = *(const uint2*)(g_bits + (size_t)(c - 1) * B_DIM + b0);
        prev_d[0] = (pw.x >> 31) ? d : 0.f;
        prev_d[1] = (pw.y >> 31) ? d : 0.f;
    }

    uint2 bwv = *(const uint2*)(g_bits + (size_t)c * B_DIM + b0);
    uint32_t bw[2] = {bwv.x, bwv.y};

    float2* __restrict__ po = (float2*)(out + (size_t)(c * CL) * B_DIM + b0);

#pragma unroll
    for (int i = 0; i < CL; ++i) {
        S = fmaf(d, S, d);  // shared across the sequences
        float ov[2];
#pragma unroll
        for (int s = 0; s < 2; ++s) {
            bool cur = (bw[s] >> i) & 1u;
            float cur_d = cur ? d : 0.f;
            float na1 = n1t[s];                          // na1_t == n1t_{t-1} (exact)
            n11[s] = fmaf(d, n11[s], cur ? prev_d[s] : 0.f);
            n1t[s] = fmaf(d, n1t[s], cur_d);
            prev_d[s] = cur_d;
            float num = (cur ? n11[s] : n1t[s] - n11[s]) + 1.f;
            float den = (cur ? na1 : S - na1) + 2.f;
            ov[s] = __fdividef(num, den);
        }
        __stcs(po + (size_t)i * (B_DIM / 2), make_float2(ov[0], ov[1]));
    }
}

// ---------------------------------------------------------------------------
extern "C" void kernel_launch(void* const* d_in, const int* in_sizes, int n_in,
                              void* d_out, int out_size) {
    const float* in   = (const float*)d_in[0];
    const float* dptr = (const float*)d_in[1];
    if (n_in >= 2 && in_sizes[0] == 1) {  // defensive: metadata order swap
        in   = (const float*)d_in[1];
        dptr = (const float*)d_in[0];
    }
    float* out = (float*)d_out;

    dim3 blk(256);
    dim3 grid1((B_DIM / 4) / 256, CHUNKS);   // (8, 128)  = 1024 blocks
    dim3 grid2(B_DIM / 256, 2);              // (32, 2)
    dim3 grid3((B_DIM / 2) / 256, CHUNKS);   // (16, 128) = 2048 blocks

    lk_pass1<<<grid1, blk>>>(in, dptr);
    lk_pass2<<<grid2, blk>>>(dptr);
    lk_pass3<<<grid3, blk>>>(dptr, out);
}